// round 17
// baseline (speedup 1.0000x reference)
#include <cuda_runtime.h>
#include <cuda_bf16.h>
#include <math.h>
#include <stdint.h>

// Problem dims (fixed)
#define HH 768
#define G3 2304          // 3*H
#define BB 64            // batch
#define LL 512           // seq len
#define NSTEP 513        // 512 steps + final end-token step
#define NROWS (NSTEP*BB)

// recurrence kernel config: 128 blocks = 64 unit-groups x 2 batch-halves
#define RBLK 128
#define RTPB 256
#define UPB  12          // units per block
#define RC   36          // gh cols per block = 3*UPB
#define RCP  40          // padded ws row: 4 groups x 10 (9 used)
#define BH   32          // batches per block
#define CHK  192         // staged k rows per buffer (768 = 4*192)

// Scratch (device globals — allocation-free rule)
static __device__ __align__(256) float g_giT[(size_t)NROWS * G3];    // [l][unit][b]
static __device__ __align__(256) float g_hT[HH * BB];                // h transposed [k][b]
static __device__ __align__(256) float g_hbm[BB * HH];
static __device__ __align__(256) float g_s1[BB * HH];
static __device__ __align__(256) float g_s2[BB * HH];
static __device__ unsigned g_leaf[16];
static __device__ unsigned g_master = 0;
static __device__ unsigned g_gen    = 0;

// ---------------------------------------------------------------------------
// packed fp32 helpers (sm_103a f32x2)
__device__ __forceinline__ void ffma2(unsigned long long& d,
                                      unsigned long long a, unsigned long long b)
{
    asm("fma.rn.f32x2 %0, %1, %2, %0;" : "+l"(d) : "l"(a), "l"(b));
}
__device__ __forceinline__ unsigned long long pack2(float x)
{
    unsigned long long r;
    asm("mov.b64 %0, {%1, %1};" : "=l"(r) : "f"(x));
    return r;
}
__device__ __forceinline__ float2 unpk2(unsigned long long v)
{
    float2 f;
    asm("mov.b64 {%0, %1}, %2;" : "=f"(f.x), "=f"(f.y) : "l"(v));
    return f;
}
__device__ __forceinline__ void cpa16(unsigned dst, const void* src)
{
    asm volatile("cp.async.cg.shared.global [%0], [%1], 16;" :: "r"(dst), "l"(src));
}
__device__ __forceinline__ void cpa_commit() { asm volatile("cp.async.commit_group;" ::: "memory"); }
__device__ __forceinline__ void cpa_wait0()  { asm volatile("cp.async.wait_group 0;" ::: "memory"); }
__device__ __forceinline__ void cpa_wait1()  { asm volatile("cp.async.wait_group 1;" ::: "memory"); }

__device__ __forceinline__ float sigmoidf_(float x)
{
    return 1.f / (1.f + __expf(-x));
}

// ---------------------------------------------------------------------------
__global__ void k_init()
{
    int t = blockIdx.x * blockDim.x + threadIdx.x;
    if (t < BB * HH) g_hT[t] = 0.f;
}

// ---------------------------------------------------------------------------
// gi producer (verbatim R15 winner): 192 units x 64 batch, 128 threads,
// FMA-bound 8-batch x 12-unit thread tile.
__global__ void __launch_bounds__(128) k_gi(const int* __restrict__ goal,
                                            const float* __restrict__ emb,
                                            const float* __restrict__ w_ih,
                                            const float* __restrict__ b_ih)
{
    __shared__ __align__(16) float As[16][192];   // units x k
    __shared__ __align__(16) float Bs[16][64];    // batch x k
    __shared__ int tok[64];

    const int by  = blockIdx.y;
    const int n0  = blockIdx.x * 192;
    const int tid = threadIdx.x;
    const bool seq = (by < LL);

    if (tid < 64) tok[tid] = seq ? goal[tid * LL + by] : 1;
    __syncthreads();

    const int bg = tid & 7;
    const int ug = tid >> 3;

    float4 vw[6], ve[2];
    auto loadW = [&](float4 v[6], int k0) {
#pragma unroll
        for (int q = 0; q < 6; q++) {
            int f = tid + 128 * q;
            int r = f >> 2, kk = (f & 3) * 4;
            v[q] = *(const float4*)(w_ih + (size_t)(n0 + r) * HH + k0 + kk);
        }
    };
    auto loadE = [&](float4 v[2], int k0) {
#pragma unroll
        for (int q = 0; q < 2; q++) {
            int f = tid + 128 * q;
            int r = f >> 2, kk = (f & 3) * 4;
            v[q] = *(const float4*)(emb + (size_t)tok[r] * HH + k0 + kk);
            if (seq) {
                v[q].x = fmaxf(v[q].x, 0.f); v[q].y = fmaxf(v[q].y, 0.f);
                v[q].z = fmaxf(v[q].z, 0.f); v[q].w = fmaxf(v[q].w, 0.f);
            }
        }
    };
    auto storeW = [&](const float4 v[6]) {
#pragma unroll
        for (int q = 0; q < 6; q++) {
            int f = tid + 128 * q;
            int r = f >> 2, kk = (f & 3) * 4;
            As[kk][r] = v[q].x; As[kk+1][r] = v[q].y; As[kk+2][r] = v[q].z; As[kk+3][r] = v[q].w;
        }
    };
    auto storeE = [&](const float4 v[2]) {
#pragma unroll
        for (int q = 0; q < 2; q++) {
            int f = tid + 128 * q;
            int r = f >> 2, kk = (f & 3) * 4;
            Bs[kk][r] = v[q].x; Bs[kk+1][r] = v[q].y; Bs[kk+2][r] = v[q].z; Bs[kk+3][r] = v[q].w;
        }
    };

    unsigned long long acc[4][12];
#pragma unroll
    for (int p = 0; p < 4; p++)
#pragma unroll
        for (int c = 0; c < 12; c++) acc[p][c] = 0ull;

    loadW(vw, 0); loadE(ve, 0);
    storeW(vw);   storeE(ve);
    __syncthreads();

    for (int t = 0; t < HH / 16; t++) {
        float4 nw[6], ne[2];
        if (t < HH / 16 - 1) { loadW(nw, (t + 1) * 16); loadE(ne, (t + 1) * 16); }
#pragma unroll 2
        for (int k = 0; k < 16; k++) {
            ulonglong2 b0 = *(const ulonglong2*)&Bs[k][bg * 8];
            ulonglong2 b1 = *(const ulonglong2*)&Bs[k][bg * 8 + 4];
            float4 a0 = *(const float4*)&As[k][ug * 12];
            float4 a1 = *(const float4*)&As[k][ug * 12 + 4];
            float4 a2 = *(const float4*)&As[k][ug * 12 + 8];
            unsigned long long ap[4] = {b0.x, b0.y, b1.x, b1.y};
            unsigned long long bp[12] = {pack2(a0.x), pack2(a0.y), pack2(a0.z), pack2(a0.w),
                                         pack2(a1.x), pack2(a1.y), pack2(a1.z), pack2(a1.w),
                                         pack2(a2.x), pack2(a2.y), pack2(a2.z), pack2(a2.w)};
#pragma unroll
            for (int p = 0; p < 4; p++)
#pragma unroll
                for (int c = 0; c < 12; c++) ffma2(acc[p][c], ap[p], bp[c]);
        }
        __syncthreads();
        if (t < HH / 16 - 1) { storeW(nw); storeE(ne); }
        __syncthreads();
    }

#pragma unroll
    for (int c = 0; c < 12; c++) {
        const int u = n0 + ug * 12 + c;
        const float bias = b_ih[u];
        float2 v0 = unpk2(acc[0][c]);
        float2 v1 = unpk2(acc[1][c]);
        float2 v2 = unpk2(acc[2][c]);
        float2 v3 = unpk2(acc[3][c]);
        float* d = g_giT + ((size_t)by * G3 + u) * BB + bg * 8;
        *(float4*)(d)     = make_float4(v0.x + bias, v0.y + bias, v1.x + bias, v1.y + bias);
        *(float4*)(d + 4) = make_float4(v2.x + bias, v2.y + bias, v3.x + bias, v3.y + bias);
    }
}

// ---------------------------------------------------------------------------
// Two-level grid barrier (verbatim from benched kernel)
__device__ __forceinline__ void gsync(unsigned target)
{
    __syncthreads();
    if (threadIdx.x == 0) {
        unsigned old;
        asm volatile("atom.acq_rel.gpu.global.add.u32 %0, [%1], %2;"
                     : "=r"(old) : "l"(g_leaf + (blockIdx.x & 15u)), "r"(1u) : "memory");
        if ((old & 7u) == 7u) {
            unsigned o2;
            asm volatile("atom.acq_rel.gpu.global.add.u32 %0, [%1], %2;"
                         : "=r"(o2) : "l"(&g_master), "r"(1u) : "memory");
            if ((o2 & 15u) == 15u)
                asm volatile("st.release.gpu.global.u32 [%0], %1;"
                             :: "l"(&g_gen), "r"(target) : "memory");
        }
        unsigned g;
        do {
            asm volatile("ld.acquire.gpu.global.u32 %0, [%1];"
                         : "=r"(g) : "l"(&g_gen) : "memory");
        } while ((int)(g - target) < 0);
    }
    __syncthreads();
}

// ---------------------------------------------------------------------------
// Persistent recurrence, batch-split: 128 blocks = 64 unit-groups x 2 batch
// halves. Block owns 12 units x 32 batches -> stages only h[*][its 32 b]
// (96KB/step, HALF the prior L2 broadcast). 8 warp k-slices, acc[2][9],
// ONE barrier per step. smem: ws 120KB + hs 2x24KB + red 36KB + ghs 4.5KB.
__global__ void __launch_bounds__(RTPB, 1) k_rec(const float* __restrict__ w_hh,
                                                 const float* __restrict__ b_hh)
{
    extern __shared__ __align__(16) float sm[];
    float* ws  = sm;                         // [768][40] padded (36 used)
    float* hs  = sm + HH * RCP;              // 2 x [192][32]
    float* red = hs + 2 * CHK * BH;          // 8 x [32][36]
    float* ghs = red + 8 * BH * RC;          // [32][36]

    const int tid  = threadIdx.x;
    const int bid  = blockIdx.x;
    const int b0   = (bid & 1) * BH;         // batch base
    const int u0   = (bid >> 1) * UPB;       // unit base
    const int w    = tid >> 5;               // warp = k-slice 0..7
    const int lane = tid & 31;
    const int rg   = lane & 7;               // batch-pairs rg*2, rg*2+1 (4 batches)
    const int cg   = lane >> 3;              // col group 0..3 -> cols cg*9..+8

    // preload w slice: ws[k*40 + g*10 + c], col = g*9+c (c<9) -> (gate, iu)
    for (int idx = tid; idx < HH * RCP; idx += RTPB) {
        int k = idx / RCP, cc = idx - k * RCP;
        int g = cc / 10, c = cc - g * 10;
        float v = 0.f;
        if (c < 9) {
            int col = g * 9 + c;                 // 0..35
            int gate = col / UPB, iu = col - gate * UPB;
            v = w_hh[(size_t)(gate * HH + u0 + iu) * HH + k];
        }
        ws[idx] = v;
    }
    // gate biases: t = tid + q*256 -> valid t < BH*UPB=384; iu = t>>5
    float bh_r[2], bh_z[2], bh_n[2];
#pragma unroll
    for (int q = 0; q < 2; q++) {
        int t = tid + q * RTPB;
        if (t < BH * UPB) {
            int iu = t >> 5;
            bh_r[q] = b_hh[u0 + iu];
            bh_z[q] = b_hh[HH + u0 + iu];
            bh_n[q] = b_hh[2 * HH + u0 + iu];
        }
    }
    __syncthreads();

    const unsigned hsb = (unsigned)__cvta_generic_to_shared(hs);
    // stage chunk ch: 192 k-rows x 32 batches (128B contiguous per row)
    auto stage = [&](int ch) {
#pragma unroll
        for (int j = 0; j < 6; j++) {
            int idx = tid + j * RTPB;            // 0..1535
            int row = idx >> 3, quad = idx & 7;
            const float* src = g_hT + (size_t)(ch * CHK + row) * BB + b0 + quad * 4;
            unsigned dst = hsb + (unsigned)((ch & 1) * (CHK * BH * 4)) + row * (BH * 4) + quad * 16;
            cpa16(dst, src);
        }
        cpa_commit();
    };

    const unsigned base = *(volatile unsigned*)&g_gen;
    unsigned ngen = 0;

    for (int l = 0; l < NSTEP; l++) {
        stage(0);
        stage(1);

        // prefetch gate operands (32 consecutive batches -> coalesced)
        float pre_r[2], pre_z[2], pre_n[2], pre_h[2];
#pragma unroll
        for (int q = 0; q < 2; q++) {
            int t = tid + q * RTPB;
            if (t < BH * UPB) {
                int b = b0 + (t & 31), iu = t >> 5;
                const float* gp = g_giT + ((size_t)l * G3 + u0 + iu) * BB + b;
                pre_r[q] = __ldcg(gp);
                pre_z[q] = __ldcg(gp + (size_t)HH * BB);
                pre_n[q] = __ldcg(gp + (size_t)2 * HH * BB);
                pre_h[q] = __ldcg(&g_hT[(u0 + iu) * BB + b]);
            }
        }

        unsigned long long acc[2][9];
#pragma unroll
        for (int p = 0; p < 2; p++)
#pragma unroll
            for (int c = 0; c < 9; c++) acc[p][c] = 0ull;

        for (int ch = 0; ch < HH / CHK; ch++) {     // 4 chunks
            if (ch < HH / CHK - 1) cpa_wait1(); else cpa_wait0();
            __syncthreads();
            const float* hb = hs + (ch & 1) * (CHK * BH);
            const int kb = w * (CHK / 8);           // 24 k per slice
#pragma unroll 4
            for (int kk = 0; kk < CHK / 8; kk++) {
                const int kl = kb + kk;
                const int kg = ch * CHK + kl;
                ulonglong2 a = *(const ulonglong2*)&hb[kl * BH + rg * 4];
                const float* wp = &ws[kg * RCP + cg * 10];
                float2 w01 = *(const float2*)(wp);
                float2 w23 = *(const float2*)(wp + 2);
                float2 w45 = *(const float2*)(wp + 4);
                float2 w67 = *(const float2*)(wp + 6);
                float  w8  = wp[8];
                unsigned long long bp[9] = {pack2(w01.x), pack2(w01.y), pack2(w23.x),
                                            pack2(w23.y), pack2(w45.x), pack2(w45.y),
                                            pack2(w67.x), pack2(w67.y), pack2(w8)};
#pragma unroll
                for (int c = 0; c < 9; c++) {
                    ffma2(acc[0][c], a.x, bp[c]);
                    ffma2(acc[1][c], a.y, bp[c]);
                }
            }
            __syncthreads();                 // buffer (ch&1) free
            if (ch < HH / CHK - 2) stage(ch + 2);
        }

        // ---- k-split reduction: red[w][32][36], then ghs[32][36] ----
#pragma unroll
        for (int p = 0; p < 2; p++) {
            const int r0 = rg * 4 + 2 * p;
#pragma unroll
            for (int c = 0; c < 9; c++) {
                float2 v = unpk2(acc[p][c]);
                red[w * (BH * RC) + r0 * RC + cg * 9 + c]       = v.x;
                red[w * (BH * RC) + (r0 + 1) * RC + cg * 9 + c] = v.y;
            }
        }
        __syncthreads();
#pragma unroll
        for (int j = 0; j < 5; j++) {                // 1152 outputs / 256 thr
            const int o = tid + j * RTPB;
            if (o < BH * RC) {
                float s = red[o];
#pragma unroll
                for (int ww = 1; ww < 8; ww++) s += red[ww * (BH * RC) + o];
                ghs[o] = s;
            }
        }
        __syncthreads();

        // ---- gates (block-local) ----
#pragma unroll
        for (int q = 0; q < 2; q++) {
            const int t = tid + q * RTPB;
            if (t < BH * UPB) {
                const int bl = t & 31, iu = t >> 5;
                const int b = b0 + bl;
                float ghr = ghs[bl * RC + iu];
                float ghz = ghs[bl * RC + UPB + iu];
                float ghn = ghs[bl * RC + 2 * UPB + iu];
                float r = sigmoidf_(pre_r[q] + ghr + bh_r[q]);
                float z = sigmoidf_(pre_z[q] + ghz + bh_z[q]);
                float n = tanhf(pre_n[q] + r * (ghn + bh_n[q]));
                float h = (1.f - z) * n + z * pre_h[q];
                if (l < LL) h = fmaxf(h, 0.f);       // final step NOT relu'd
                __stcg(&g_hT[(u0 + iu) * BB + b], h);
                if (l == LL) g_hbm[(size_t)b * HH + u0 + iu] = h;
            }
        }

        ++ngen;
        gsync(base + ngen);   // ONE barrier per step
    }
}

// ---------------------------------------------------------------------------
// Scorer (verbatim; device globals referenced in device code)
__global__ void __launch_bounds__(256) k_mlp0(const float* __restrict__ w,
                                              const float* __restrict__ bias)
{
    const int warp = threadIdx.x >> 5;
    const int lane = threadIdx.x & 31;
    const int n = blockIdx.x * 8 + warp;

    float4 wr[6];
    const float* wrow = w + (size_t)n * HH + lane * 24;
#pragma unroll
    for (int i = 0; i < 6; i++) wr[i] = *(const float4*)(wrow + i * 4);
    const float bn = bias[n];

    for (int b = 0; b < BB; b++) {
        const float* xr = g_hbm + (size_t)b * HH + lane * 24;
        float s = 0.f;
#pragma unroll
        for (int i = 0; i < 6; i++) {
            float4 xv = *(const float4*)(xr + i * 4);
            s += xv.x * wr[i].x + xv.y * wr[i].y + xv.z * wr[i].z + xv.w * wr[i].w;
        }
#pragma unroll
        for (int off = 16; off; off >>= 1) s += __shfl_xor_sync(0xffffffffu, s, off);
        if (lane == 0) g_s1[(size_t)b * HH + n] = fmaxf(s + bn, 0.f);
    }
}

__global__ void __launch_bounds__(256) k_mlp1(const float* __restrict__ w,
                                              const float* __restrict__ bias)
{
    const int warp = threadIdx.x >> 5;
    const int lane = threadIdx.x & 31;
    const int n = blockIdx.x * 8 + warp;

    float4 wr[6];
    const float* wrow = w + (size_t)n * HH + lane * 24;
#pragma unroll
    for (int i = 0; i < 6; i++) wr[i] = *(const float4*)(wrow + i * 4);
    const float bn = bias[n];

    for (int b = 0; b < BB; b++) {
        const float* xr = g_s1 + (size_t)b * HH + lane * 24;
        float s = 0.f;
#pragma unroll
        for (int i = 0; i < 6; i++) {
            float4 xv = *(const float4*)(xr + i * 4);
            s += xv.x * wr[i].x + xv.y * wr[i].y + xv.z * wr[i].z + xv.w * wr[i].w;
        }
#pragma unroll
        for (int off = 16; off; off >>= 1) s += __shfl_xor_sync(0xffffffffu, s, off);
        if (lane == 0) g_s2[(size_t)b * HH + n] = fmaxf(s + bn, 0.f);
    }
}

__global__ void __launch_bounds__(256) k_final(const float* __restrict__ swo,
                                               const float* __restrict__ sbo,
                                               float* __restrict__ out)
{
    const int warp = threadIdx.x >> 5;
    const int lane = threadIdx.x & 31;
    const int b = blockIdx.x * 8 + warp;
    const float* xr = g_s2 + (size_t)b * HH + lane * 24;
    const float* wr = swo + lane * 24;
    float s = 0.f;
#pragma unroll
    for (int i = 0; i < 6; i++) {
        float4 xv = *(const float4*)(xr + i * 4);
        float4 wv = *(const float4*)(wr + i * 4);
        s += xv.x * wv.x + xv.y * wv.y + xv.z * wv.z + xv.w * wv.w;
    }
#pragma unroll
    for (int off = 16; off; off >>= 1) s += __shfl_xor_sync(0xffffffffu, s, off);
    if (lane == 0) out[b] = s + sbo[0];
}

// ---------------------------------------------------------------------------
extern "C" void kernel_launch(void* const* d_in, const int* in_sizes, int n_in,
                              void* d_out, int out_size)
{
    const int*   goal = (const int*)  d_in[0];
    const float* emb  = (const float*)d_in[1];
    const float* w_ih = (const float*)d_in[2];
    const float* w_hh = (const float*)d_in[3];
    const float* b_ih = (const float*)d_in[4];
    const float* b_hh = (const float*)d_in[5];
    const float* sw0  = (const float*)d_in[6];
    const float* sb0  = (const float*)d_in[7];
    const float* sw1  = (const float*)d_in[8];
    const float* sb1  = (const float*)d_in[9];
    const float* swo  = (const float*)d_in[10];
    const float* sbo  = (const float*)d_in[11];
    float* out = (float*)d_out;

    // ws 120KB + hs 48KB + red 36KB + ghs 4.5KB = 208.5KB
    const int smem_rec = (HH * RCP + 2 * CHK * BH + 8 * BH * RC + BH * RC)
                         * (int)sizeof(float);
    cudaFuncSetAttribute(k_rec, cudaFuncAttributeMaxDynamicSharedMemorySize, smem_rec);

    k_init<<<(BB * HH + 255) / 256, 256>>>();
    k_gi<<<dim3(G3 / 192, NSTEP), 128>>>(goal, emb, w_ih, b_ih);
    k_rec<<<RBLK, RTPB, smem_rec>>>(w_hh, b_hh);
    k_mlp0<<<HH / 8, 256>>>(sw0, sb0);
    k_mlp1<<<HH / 8, 256>>>(sw1, sb1);
    k_final<<<BB / 8, 256>>>(swo, sbo, out);
}